// round 1
// baseline (speedup 1.0000x reference)
#include <cuda_runtime.h>
#include <math.h>

#define N_NODES 100000
#define NFEAT   256
#define NHID    8
#define HEADS   8
#define HC      64      // HEADS*NHID
#define NCLASS  32
#define NEG     0.2f

// ---------------- scratch (static __device__ globals, ~95 MB) ----------------
__device__ float d_h1   [N_NODES * HC];
__device__ float d_als1 [N_NODES * HEADS];
__device__ float d_ald1 [N_NODES * HEADS];
__device__ int   d_m1   [N_NODES * HEADS];
__device__ float d_s1   [N_NODES * HEADS];
__device__ float d_sinv1[N_NODES * HEADS];
__device__ float d_out1 [N_NODES * HC];
__device__ float d_g    [N_NODES * NCLASS];
__device__ float d_als2 [N_NODES];
__device__ float d_ald2 [N_NODES];
__device__ int   d_m2   [N_NODES];
__device__ float d_s2   [N_NODES];
__device__ float d_sinv2[N_NODES];
__device__ float d_out2 [N_NODES * NCLASS];
__device__ int   d_is64;

// order-preserving float<->int encode for atomicMax on signed floats
__device__ __forceinline__ int   fenc(float f){ int i = __float_as_int(f); return i >= 0 ? i : i ^ 0x7fffffff; }
__device__ __forceinline__ float fdec(int i)  { return __int_as_float(i >= 0 ? i : i ^ 0x7fffffff); }
__device__ __forceinline__ float lrelu(float x){ return x >= 0.f ? x : NEG * x; }

__device__ __forceinline__ void load_edge(const void* ei, int E, int e, int& s, int& d) {
    if (d_is64) {
        const long long* p = (const long long*)ei;
        s = (int)p[e]; d = (int)p[E + e];
    } else {
        const int* p = (const int*)ei;
        s = p[e]; d = p[E + e];
    }
}

// Detect whether edge_index is int64 (odd 32-bit words all zero) or int32.
__global__ void k_detect(const void* ei) {
    const int* p = (const int*)ei;
    d_is64 = (p[1] == 0 && p[3] == 0 && p[5] == 0 && p[7] == 0) ? 1 : 0;
}

// ---------------- K1: h1 = x @ W1 ; attention logits ; m1 self-init ----------
// block = 256 threads = 4 subgroups x 64 cols; each subgroup handles 4 nodes.
__global__ void __launch_bounds__(256) k1_gemm1(
    const float* __restrict__ x, const float* __restrict__ W1,
    const float* __restrict__ a_s, const float* __restrict__ a_d)
{
    __shared__ float xs[16 * NFEAT];
    int base = blockIdx.x * 16;
    int tid  = threadIdx.x;

    const float4* xg  = (const float4*)(x + (size_t)base * NFEAT);
    float4*       xs4 = (float4*)xs;
    #pragma unroll
    for (int r = 0; r < 4; r++) xs4[tid + 256 * r] = xg[tid + 256 * r];
    __syncthreads();

    int c   = tid & 63;
    int sub = tid >> 6;
    const float* xr = xs + sub * 4 * NFEAT;

    float acc0 = 0.f, acc1 = 0.f, acc2 = 0.f, acc3 = 0.f;
    #pragma unroll 8
    for (int k = 0; k < NFEAT; k++) {
        float w = W1[k * 64 + c];
        acc0 += xr[k            ] * w;
        acc1 += xr[NFEAT     + k] * w;
        acc2 += xr[2 * NFEAT + k] * w;
        acc3 += xr[3 * NFEAT + k] * w;
    }
    float accs[4] = {acc0, acc1, acc2, acc3};

    int   h    = c >> 3;
    float as_w = a_s[c];   // a_src1[h][c&7]
    float ad_w = a_d[c];

    #pragma unroll
    for (int j = 0; j < 4; j++) {
        int node = base + sub * 4 + j;
        d_h1[node * 64 + c] = accs[j];
        float ps = accs[j] * as_w;
        float pd = accs[j] * ad_w;
        #pragma unroll
        for (int o = 4; o > 0; o >>= 1) {
            ps += __shfl_xor_sync(0xffffffffu, ps, o, 8);
            pd += __shfl_xor_sync(0xffffffffu, pd, o, 8);
        }
        if ((c & 7) == 0) {
            d_als1[node * 8 + h] = ps;
            d_ald1[node * 8 + h] = pd;
            d_m1  [node * 8 + h] = fenc(lrelu(ps + pd));   // self-loop init
        }
    }
}

// ---------------- K2: layer-1 segment max over edges -------------------------
__global__ void k2_max1(const void* __restrict__ ei, int E) {
    int t = blockIdx.x * blockDim.x + threadIdx.x;
    if (t >= E * 8) return;
    int e = t >> 3, h = t & 7;
    int s, d; load_edge(ei, E, e, s, d);
    float ev = lrelu(d_als1[s * 8 + h] + d_ald1[d * 8 + h]);
    atomicMax(&d_m1[d * 8 + h], fenc(ev));
}

// ---------------- s1 init with self contribution -----------------------------
__global__ void k_sinit1() {
    int t = blockIdx.x * blockDim.x + threadIdx.x;
    if (t >= N_NODES * 8) return;
    float e = lrelu(d_als1[t] + d_ald1[t]);
    d_s1[t] = expf(e - fdec(d_m1[t]));
}

// ---------------- K3: layer-1 segment sum ------------------------------------
__global__ void k3_sum1(const void* __restrict__ ei, int E) {
    int t = blockIdx.x * blockDim.x + threadIdx.x;
    if (t >= E * 8) return;
    int e = t >> 3, h = t & 7;
    int s, d; load_edge(ei, E, e, s, d);
    float ev = lrelu(d_als1[s * 8 + h] + d_ald1[d * 8 + h]);
    atomicAdd(&d_s1[d * 8 + h], expf(ev - fdec(d_m1[d * 8 + h])));
}

// ---------------- out1 init with self contribution + sinv1 -------------------
__global__ void k_oinit1() {
    int t = blockIdx.x * blockDim.x + threadIdx.x;
    if (t >= N_NODES * 64) return;
    int node = t >> 6, c = t & 63, h = c >> 3;
    float s    = d_s1[node * 8 + h];
    float sinv = 1.f / (s + 1e-16f);
    float m    = fdec(d_m1[node * 8 + h]);
    float es   = lrelu(d_als1[node * 8 + h] + d_ald1[node * 8 + h]);
    float alpha = expf(es - m) * sinv;
    d_out1[t] = d_h1[t] * alpha;
    if ((c & 7) == 0) d_sinv1[node * 8 + h] = sinv;
}

// ---------------- K4: layer-1 weighted aggregation (dominant kernel) ---------
__global__ void k4_agg1(const void* __restrict__ ei, int E) {
    int t = blockIdx.x * blockDim.x + threadIdx.x;
    if (t >= E * 64) return;
    int e = t >> 6, c = t & 63, h = c >> 3;
    int s, d; load_edge(ei, E, e, s, d);
    float ev    = lrelu(d_als1[s * 8 + h] + d_ald1[d * 8 + h]);
    float alpha = expf(ev - fdec(d_m1[d * 8 + h])) * d_sinv1[d * 8 + h];
    atomicAdd(&d_out1[d * 64 + c], d_h1[s * 64 + c] * alpha);
}

// ---------------- K5: bias+ELU, g = h2 @ W2, layer-2 logits, m2 self-init ----
__global__ void __launch_bounds__(64) k5_prep2(
    const float* __restrict__ b1, const float* __restrict__ W2,
    const float* __restrict__ a_s2, const float* __restrict__ a_d2)
{
    __shared__ float h2[64];
    int n = blockIdx.x;
    int c = threadIdx.x;
    float v = d_out1[n * 64 + c] + b1[c];
    v = v > 0.f ? v : expm1f(v);         // ELU
    h2[c] = v;
    __syncthreads();
    if (c < 32) {
        float g = 0.f;
        #pragma unroll
        for (int k = 0; k < 64; k++) g += h2[k] * W2[k * 32 + c];
        d_g[n * 32 + c] = g;
        float ps = g * a_s2[c];
        float pd = g * a_d2[c];
        #pragma unroll
        for (int o = 16; o > 0; o >>= 1) {
            ps += __shfl_xor_sync(0xffffffffu, ps, o);
            pd += __shfl_xor_sync(0xffffffffu, pd, o);
        }
        if (c == 0) {
            d_als2[n] = ps; d_ald2[n] = pd;
            d_m2[n] = fenc(lrelu(ps + pd));
        }
    }
}

// ---------------- K6: layer-2 segment max ------------------------------------
__global__ void k6_max2(const void* __restrict__ ei, int E) {
    int e = blockIdx.x * blockDim.x + threadIdx.x;
    if (e >= E) return;
    int s, d; load_edge(ei, E, e, s, d);
    atomicMax(&d_m2[d], fenc(lrelu(d_als2[s] + d_ald2[d])));
}

__global__ void k_sinit2() {
    int n = blockIdx.x * blockDim.x + threadIdx.x;
    if (n >= N_NODES) return;
    float e = lrelu(d_als2[n] + d_ald2[n]);
    d_s2[n] = expf(e - fdec(d_m2[n]));
}

// ---------------- K8: layer-2 segment sum ------------------------------------
__global__ void k8_sum2(const void* __restrict__ ei, int E) {
    int e = blockIdx.x * blockDim.x + threadIdx.x;
    if (e >= E) return;
    int s, d; load_edge(ei, E, e, s, d);
    float ev = lrelu(d_als2[s] + d_ald2[d]);
    atomicAdd(&d_s2[d], expf(ev - fdec(d_m2[d])));
}

__global__ void k_oinit2() {
    int t = blockIdx.x * blockDim.x + threadIdx.x;
    if (t >= N_NODES * 32) return;
    int node = t >> 5, c = t & 31;
    float sinv = 1.f / (d_s2[node] + 1e-16f);
    float es   = lrelu(d_als2[node] + d_ald2[node]);
    float alpha = expf(es - fdec(d_m2[node])) * sinv;
    d_out2[t] = d_g[t] * alpha;
    if (c == 0) d_sinv2[node] = sinv;
}

// ---------------- K10: layer-2 weighted aggregation --------------------------
__global__ void k10_agg2(const void* __restrict__ ei, int E) {
    int t = blockIdx.x * blockDim.x + threadIdx.x;
    if (t >= E * 32) return;
    int e = t >> 5, c = t & 31;
    int s, d; load_edge(ei, E, e, s, d);
    float ev    = lrelu(d_als2[s] + d_ald2[d]);
    float alpha = expf(ev - fdec(d_m2[d])) * d_sinv2[d];
    atomicAdd(&d_out2[d * 32 + c], d_g[s * 32 + c] * alpha);
}

// ---------------- K11: + b2, log_softmax -------------------------------------
__global__ void __launch_bounds__(256) k11_lsm(const float* __restrict__ b2, float* __restrict__ out) {
    int t = blockIdx.x * blockDim.x + threadIdx.x;
    if (t >= N_NODES * 32) return;
    int node = t >> 5, c = t & 31;
    float v = d_out2[node * 32 + c] + b2[c];
    float mx = v;
    #pragma unroll
    for (int o = 16; o > 0; o >>= 1) mx = fmaxf(mx, __shfl_xor_sync(0xffffffffu, mx, o));
    float se = expf(v - mx);
    #pragma unroll
    for (int o = 16; o > 0; o >>= 1) se += __shfl_xor_sync(0xffffffffu, se, o);
    out[t] = v - mx - logf(se);
}

// ---------------- launch ------------------------------------------------------
extern "C" void kernel_launch(void* const* d_in, const int* in_sizes, int n_in,
                              void* d_out, int out_size)
{
    const float* x   = (const float*)d_in[0];
    const void*  ei  = d_in[1];
    const float* W1  = (const float*)d_in[2];
    const float* as1 = (const float*)d_in[3];
    const float* ad1 = (const float*)d_in[4];
    const float* b1  = (const float*)d_in[5];
    const float* W2  = (const float*)d_in[6];
    const float* as2 = (const float*)d_in[7];
    const float* ad2 = (const float*)d_in[8];
    const float* b2  = (const float*)d_in[9];
    float* out = (float*)d_out;

    int E = in_sizes[1] / 2;

    k_detect<<<1, 1>>>(ei);
    k1_gemm1<<<N_NODES / 16, 256>>>(x, W1, as1, ad1);
    k2_max1 <<<(E * 8 + 255) / 256, 256>>>(ei, E);
    k_sinit1<<<(N_NODES * 8 + 255) / 256, 256>>>();
    k3_sum1 <<<(E * 8 + 255) / 256, 256>>>(ei, E);
    k_oinit1<<<(N_NODES * 64 + 255) / 256, 256>>>();
    k4_agg1 <<<(E * 64 + 255) / 256, 256>>>(ei, E);
    k5_prep2<<<N_NODES, 64>>>(b1, W2, as2, ad2);
    k6_max2 <<<(E + 255) / 256, 256>>>(ei, E);
    k_sinit2<<<(N_NODES + 255) / 256, 256>>>();
    k8_sum2 <<<(E + 255) / 256, 256>>>(ei, E);
    k_oinit2<<<(N_NODES * 32 + 255) / 256, 256>>>();
    k10_agg2<<<(E * 32 + 255) / 256, 256>>>(ei, E);
    k11_lsm <<<(N_NODES * 32 + 255) / 256, 256>>>(b2, out);
}

// round 2
// speedup vs baseline: 2.0285x; 2.0285x over previous
#include <cuda_runtime.h>
#include <math.h>

#define N_NODES 100000
#define NFEAT   256
#define NHID    8
#define HEADS   8
#define HC      64      // HEADS*NHID
#define NCLASS  32
#define NEG     0.2f
#define MAX_E   1700000

// ---------------- scratch (static __device__ globals) ----------------
__device__ float d_h1  [N_NODES * HC];      // layer1 features (gather source)
__device__ float d_out1[N_NODES * HC];      // unnormalized aggregate (init = self msg)
__device__ float d_als1[N_NODES * HEADS];
__device__ float d_ald1[N_NODES * HEADS];
__device__ float d_s1  [N_NODES * HEADS];   // softmax denominators (init = 1)
__device__ float d_g   [N_NODES * NCLASS];  // layer2 features
__device__ float d_out2[N_NODES * NCLASS];
__device__ float d_als2[N_NODES];
__device__ float d_ald2[N_NODES];
__device__ float d_s2  [N_NODES];
__device__ int2  d_edge[MAX_E];
__device__ int   d_is64;

__device__ __forceinline__ float lrelu(float x){ return x >= 0.f ? x : NEG * x; }

__device__ __forceinline__ void red_v4(float* p, float a, float b, float c, float d) {
    asm volatile("red.global.add.v4.f32 [%0], {%1,%2,%3,%4};"
                 :: "l"(p), "f"(a), "f"(b), "f"(c), "f"(d) : "memory");
}

// Detect whether edge_index is int64 (odd 32-bit words all zero) or int32.
__global__ void k_detect(const void* ei) {
    const int* p = (const int*)ei;
    d_is64 = (p[1] == 0 && p[3] == 0 && p[5] == 0 && p[7] == 0) ? 1 : 0;
}

// Convert to packed int2 (src,dst) per edge.
__global__ void k_conv(const void* __restrict__ ei, int E) {
    int e = blockIdx.x * blockDim.x + threadIdx.x;
    if (e >= E) return;
    int s, d;
    if (d_is64) {
        const long long* p = (const long long*)ei;
        s = (int)p[e]; d = (int)p[E + e];
    } else {
        const int* p = (const int*)ei;
        s = p[e]; d = p[E + e];
    }
    d_edge[e] = make_int2(s, d);
}

// ---------------- K1: h1 = x @ W1 ; logits ; init out1 = self msg, s1 = 1 ----
__global__ void __launch_bounds__(256) k1_gemm1(
    const float* __restrict__ x, const float* __restrict__ W1,
    const float* __restrict__ a_s, const float* __restrict__ a_d)
{
    __shared__ float xs[16 * NFEAT];
    int base = blockIdx.x * 16;
    int tid  = threadIdx.x;

    const float4* xg  = (const float4*)(x + (size_t)base * NFEAT);
    float4*       xs4 = (float4*)xs;
    #pragma unroll
    for (int r = 0; r < 4; r++) xs4[tid + 256 * r] = xg[tid + 256 * r];
    __syncthreads();

    int c   = tid & 63;
    int sub = tid >> 6;
    const float* xr = xs + sub * 4 * NFEAT;

    float acc0 = 0.f, acc1 = 0.f, acc2 = 0.f, acc3 = 0.f;
    #pragma unroll 8
    for (int k = 0; k < NFEAT; k++) {
        float w = W1[k * 64 + c];
        acc0 += xr[k            ] * w;
        acc1 += xr[NFEAT     + k] * w;
        acc2 += xr[2 * NFEAT + k] * w;
        acc3 += xr[3 * NFEAT + k] * w;
    }
    float accs[4] = {acc0, acc1, acc2, acc3};

    int   h    = c >> 3;
    float as_w = a_s[c];
    float ad_w = a_d[c];

    #pragma unroll
    for (int j = 0; j < 4; j++) {
        int node = base + sub * 4 + j;
        d_h1  [node * 64 + c] = accs[j];
        d_out1[node * 64 + c] = accs[j];     // self message (weight exp(0)=1)
        float ps = accs[j] * as_w;
        float pd = accs[j] * ad_w;
        #pragma unroll
        for (int o = 4; o > 0; o >>= 1) {
            ps += __shfl_xor_sync(0xffffffffu, ps, o, 8);
            pd += __shfl_xor_sync(0xffffffffu, pd, o, 8);
        }
        if ((c & 7) == 0) {
            d_als1[node * 8 + h] = ps;
            d_ald1[node * 8 + h] = pd;
            d_s1  [node * 8 + h] = 1.f;      // self term
        }
    }
}

// ---------------- KE1: fused layer-1 edge pass (8 threads / edge) ------------
// thread t (0..7) = head t, channels 8t..8t+7. Shift = self score of dst.
__global__ void __launch_bounds__(256) kE1(int E) {
    int tid = blockIdx.x * blockDim.x + threadIdx.x;
    int e = tid >> 3;
    if (e >= E) return;
    int t = tid & 7;
    int2 ed = d_edge[e];
    int s = ed.x, d = ed.y;

    float als_s = d_als1[s * 8 + t];
    float ald_d = d_ald1[d * 8 + t];
    float als_d = d_als1[d * 8 + t];
    float m     = lrelu(als_d + ald_d);              // self score of dst (shift)
    float w     = __expf(lrelu(als_s + ald_d) - m);

    const float4* hv = (const float4*)(d_h1 + s * 64 + t * 8);
    float4 h0 = hv[0], h1 = hv[1];
    float* op = d_out1 + d * 64 + t * 8;
    red_v4(op,     w * h0.x, w * h0.y, w * h0.z, w * h0.w);
    red_v4(op + 4, w * h1.x, w * h1.y, w * h1.z, w * h1.w);

    // per-head denominators: threads 0 and 4 gather 4 w's and do one v4 red
    int lane = threadIdx.x & 31;
    int base = lane & ~7;
    float w0 = __shfl_sync(0xffffffffu, w, base + (t & 4) + 0);
    float w1 = __shfl_sync(0xffffffffu, w, base + (t & 4) + 1);
    float w2 = __shfl_sync(0xffffffffu, w, base + (t & 4) + 2);
    float w3 = __shfl_sync(0xffffffffu, w, base + (t & 4) + 3);
    if ((t & 3) == 0)
        red_v4(d_s1 + d * 8 + (t & 4), w0, w1, w2, w3);
}

// ---------------- K5: normalize + bias + ELU, g = h2 @ W2, logits, init ------
// 256 threads = 4 nodes x 64
__global__ void __launch_bounds__(256) k5_prep2(
    const float* __restrict__ b1, const float* __restrict__ W2,
    const float* __restrict__ a_s2, const float* __restrict__ a_d2)
{
    __shared__ float h2[4][64];
    int n = blockIdx.x * 4 + (threadIdx.x >> 6);
    int c = threadIdx.x & 63;
    int h = c >> 3;
    float sinv = 1.f / (d_s1[n * 8 + h] + 1e-16f);
    float v = d_out1[n * 64 + c] * sinv + b1[c];
    v = v > 0.f ? v : expm1f(v);         // ELU
    h2[threadIdx.x >> 6][c] = v;
    __syncthreads();
    if (c < 32) {
        const float* hr = h2[threadIdx.x >> 6];
        float g = 0.f;
        #pragma unroll
        for (int k = 0; k < 64; k++) g += hr[k] * W2[k * 32 + c];
        d_g   [n * 32 + c] = g;
        d_out2[n * 32 + c] = g;           // self message
        float ps = g * a_s2[c];
        float pd = g * a_d2[c];
        #pragma unroll
        for (int o = 16; o > 0; o >>= 1) {
            ps += __shfl_xor_sync(0xffffffffu, ps, o);
            pd += __shfl_xor_sync(0xffffffffu, pd, o);
        }
        if (c == 0) {
            d_als2[n] = ps; d_ald2[n] = pd;
            d_s2[n] = 1.f;                // self term
        }
    }
}

// ---------------- KE2: fused layer-2 edge pass (8 threads / edge) ------------
__global__ void __launch_bounds__(256) kE2(int E) {
    int tid = blockIdx.x * blockDim.x + threadIdx.x;
    int e = tid >> 3;
    if (e >= E) return;
    int t = tid & 7;
    int2 ed = d_edge[e];
    int s = ed.x, d = ed.y;

    float m = lrelu(d_als2[d] + d_ald2[d]);
    float w = __expf(lrelu(d_als2[s] + d_ald2[d]) - m);

    float4 g = ((const float4*)(d_g + s * 32))[t >> 1];   // wait: need per-thread chunk
    // each thread handles 4 channels: c4 = t*4
    g = ((const float4*)(d_g + s * 32))[t];
    red_v4(d_out2 + d * 32 + t * 4, w * g.x, w * g.y, w * g.z, w * g.w);
    if (t == 0) atomicAdd(d_s2 + d, w);
}

// ---------------- K11: normalize + b2 + log_softmax --------------------------
__global__ void __launch_bounds__(256) k11_lsm(const float* __restrict__ b2,
                                               float* __restrict__ out) {
    int t = blockIdx.x * blockDim.x + threadIdx.x;
    if (t >= N_NODES * 32) return;
    int node = t >> 5, c = t & 31;
    float sinv = 1.f / (d_s2[node] + 1e-16f);
    float v = d_out2[t] * sinv + b2[c];
    float mx = v;
    #pragma unroll
    for (int o = 16; o > 0; o >>= 1) mx = fmaxf(mx, __shfl_xor_sync(0xffffffffu, mx, o));
    float se = __expf(v - mx);
    #pragma unroll
    for (int o = 16; o > 0; o >>= 1) se += __shfl_xor_sync(0xffffffffu, se, o);
    out[t] = v - mx - __logf(se);
}

// ---------------- launch ------------------------------------------------------
extern "C" void kernel_launch(void* const* d_in, const int* in_sizes, int n_in,
                              void* d_out, int out_size)
{
    const float* x   = (const float*)d_in[0];
    const void*  ei  = d_in[1];
    const float* W1  = (const float*)d_in[2];
    const float* as1 = (const float*)d_in[3];
    const float* ad1 = (const float*)d_in[4];
    const float* b1  = (const float*)d_in[5];
    const float* W2  = (const float*)d_in[6];
    const float* as2 = (const float*)d_in[7];
    const float* ad2 = (const float*)d_in[8];
    const float* b2  = (const float*)d_in[9];
    float* out = (float*)d_out;

    int E = in_sizes[1] / 2;

    k_detect<<<1, 1>>>(ei);
    k_conv  <<<(E + 255) / 256, 256>>>(ei, E);
    k1_gemm1<<<N_NODES / 16, 256>>>(x, W1, as1, ad1);
    kE1     <<<(E * 8 + 255) / 256, 256>>>(E);
    k5_prep2<<<N_NODES / 4, 256>>>(b1, W2, as2, ad2);
    kE2     <<<(E * 8 + 255) / 256, 256>>>(E);
    k11_lsm <<<(N_NODES * 32 + 255) / 256, 256>>>(b2, out);
}

// round 3
// speedup vs baseline: 2.1408x; 1.0553x over previous
#include <cuda_runtime.h>
#include <math.h>

#define N_NODES 100000
#define NFEAT   256
#define HEADS   8
#define HC      64
#define NCLASS  32
#define NEG     0.2f
#define MAX_E   1700000

typedef unsigned long long ull;

// ---------------- scratch ----------------
__device__ float d_h1  [N_NODES * HC];
__device__ float d_h2  [N_NODES * HC];
__device__ float d_als1[N_NODES * HEADS];
__device__ float d_ald1[N_NODES * HEADS];
__device__ float d_m1  [N_NODES * HEADS];
__device__ float d_g   [N_NODES * NCLASS];
__device__ float d_als2[N_NODES];
__device__ float d_ald2[N_NODES];
__device__ float d_m2  [N_NODES];
__device__ int2  d_edge[MAX_E];
__device__ int   d_esrc[MAX_E + 32];
__device__ int   d_deg [N_NODES];
__device__ int   d_rowptr[N_NODES + 1];
__device__ int   d_cursor[N_NODES + 1];
__device__ int   d_bsum[128];
__device__ int   d_is64;

__device__ __forceinline__ float lrelu(float x){ return x >= 0.f ? x : NEG * x; }

__device__ __forceinline__ ull pack2(float x){
    ull r; asm("mov.b64 %0, {%1, %1};" : "=l"(r) : "f"(x)); return r;
}
__device__ __forceinline__ void fma2(ull& d, ull a, ull b){
    asm("fma.rn.f32x2 %0, %1, %2, %0;" : "+l"(d) : "l"(a), "l"(b));
}
__device__ __forceinline__ void unpack2(ull v, float& lo, float& hi){
    asm("mov.b64 {%0, %1}, %2;" : "=f"(lo), "=f"(hi) : "l"(v));
}

// ---------------- edge-index prep + CSR build ----------------
__global__ void k_detect(const void* ei) {
    const int* p = (const int*)ei;
    d_is64 = (p[1] == 0 && p[3] == 0 && p[5] == 0 && p[7] == 0) ? 1 : 0;
}

__global__ void k_zero() {
    int i = blockIdx.x * blockDim.x + threadIdx.x;
    if (i < N_NODES) d_deg[i] = 0;
}

__global__ void k_conv(const void* __restrict__ ei, int E) {
    int e = blockIdx.x * blockDim.x + threadIdx.x;
    if (e >= E) return;
    int s, d;
    if (d_is64) {
        const long long* p = (const long long*)ei;
        s = (int)p[e]; d = (int)p[E + e];
    } else {
        const int* p = (const int*)ei;
        s = p[e]; d = p[E + e];
    }
    d_edge[e] = make_int2(s, d);
    atomicAdd(&d_deg[d], 1);
}

__global__ void __launch_bounds__(1024) kscan1(int nElem) {
    __shared__ int wsum[32], wbase[32];
    int i = blockIdx.x * 1024 + threadIdx.x;
    int v = (i < nElem) ? d_deg[i] : 0;
    int lane = threadIdx.x & 31, w = threadIdx.x >> 5;
    int incl = v;
    #pragma unroll
    for (int o = 1; o < 32; o <<= 1) {
        int t = __shfl_up_sync(0xffffffffu, incl, o);
        if (lane >= o) incl += t;
    }
    if (lane == 31) wsum[w] = incl;
    __syncthreads();
    if (w == 0) {
        int s = wsum[lane], si = s;
        #pragma unroll
        for (int o = 1; o < 32; o <<= 1) {
            int t = __shfl_up_sync(0xffffffffu, si, o);
            if (lane >= o) si += t;
        }
        wbase[lane] = si - s;
    }
    __syncthreads();
    int excl = incl - v + wbase[w];
    if (i < nElem) d_rowptr[i] = excl;
    if (threadIdx.x == 1023) d_bsum[blockIdx.x] = excl + v;
}

__global__ void kscan2(int nb) {
    __shared__ int sm[128];
    int t = threadIdx.x;
    int v = (t < nb) ? d_bsum[t] : 0;
    sm[t] = v;
    __syncthreads();
    for (int o = 1; o < 128; o <<= 1) {
        int tmp = (t >= o) ? sm[t - o] : 0;
        __syncthreads();
        sm[t] += tmp;
        __syncthreads();
    }
    if (t < nb) d_bsum[t] = sm[t] - v;
}

__global__ void kscan3(int E) {
    int i = blockIdx.x * blockDim.x + threadIdx.x;
    if (i < N_NODES) {
        int r = d_rowptr[i] + d_bsum[i >> 10];
        d_rowptr[i] = r;
        d_cursor[i] = r;
    } else if (i == N_NODES) {
        d_rowptr[N_NODES] = E;
    }
}

__global__ void k_scat(int E) {
    int e = blockIdx.x * blockDim.x + threadIdx.x;
    if (e >= E) return;
    int2 ed = d_edge[e];
    int pos = atomicAdd(&d_cursor[ed.y], 1);
    d_esrc[pos] = ed.x;
}

// ---------------- K1: h1 = x @ W1 (f32x2 packed), logits, m1 ----------------
// block = 128 threads, tile = 32 nodes x 64 cols. tx=tid&15 (cols tx+16j),
// ty=tid>>4 (nodes 4ty..4ty+3 as two f32x2 pairs).
#define XS_STRIDE 34
#define WS_STRIDE 65
#define HS_STRIDE 68
#define SMEM_K1 ((256*XS_STRIDE + 256*WS_STRIDE + 32*HS_STRIDE) * 4)

__global__ void __launch_bounds__(128) k1_gemm1(
    const float* __restrict__ x, const float* __restrict__ W1,
    const float* __restrict__ a_s, const float* __restrict__ a_d)
{
    extern __shared__ float smem[];
    float* xs = smem;                    // [256][34]
    float* ws = xs + 256 * XS_STRIDE;    // [256][65]
    float* hs = ws + 256 * WS_STRIDE;    // [32][68]

    int t = threadIdx.x;
    int base = blockIdx.x * 32;
    int tx = t & 15, ty = t >> 4;

    // load x tile transposed: xs[k][n] = x[base+n][k]
    #pragma unroll
    for (int r = 0; r < 16; r++) {
        int idx = r * 128 + t;
        int n = idx & 31, kq = idx >> 5;
        float4 xv = *(const float4*)(x + (size_t)(base + n) * NFEAT + kq * 4);
        xs[(4*kq+0)*XS_STRIDE + n] = xv.x;
        xs[(4*kq+1)*XS_STRIDE + n] = xv.y;
        xs[(4*kq+2)*XS_STRIDE + n] = xv.z;
        xs[(4*kq+3)*XS_STRIDE + n] = xv.w;
    }
    // load W1 (256x64) into ws
    #pragma unroll
    for (int r = 0; r < 32; r++) {
        int idx4 = r * 128 + t;
        int k = idx4 >> 4, c4 = (idx4 & 15) * 4;
        float4 wv = ((const float4*)W1)[idx4];
        ws[k*WS_STRIDE + c4 + 0] = wv.x;
        ws[k*WS_STRIDE + c4 + 1] = wv.y;
        ws[k*WS_STRIDE + c4 + 2] = wv.z;
        ws[k*WS_STRIDE + c4 + 3] = wv.w;
    }
    __syncthreads();

    ull acc[8];
    #pragma unroll
    for (int i = 0; i < 8; i++) acc[i] = 0;

    int xoff = 4 * ty;
    #pragma unroll 4
    for (int k = 0; k < NFEAT; k++) {
        const float* xk = xs + k * XS_STRIDE + xoff;
        ull xA = *(const ull*)xk;
        ull xB = *(const ull*)(xk + 2);
        const float* wk = ws + k * WS_STRIDE + tx;
        ull w0 = pack2(wk[0]), w1 = pack2(wk[16]), w2 = pack2(wk[32]), w3 = pack2(wk[48]);
        fma2(acc[0], xA, w0); fma2(acc[1], xA, w1);
        fma2(acc[2], xA, w2); fma2(acc[3], xA, w3);
        fma2(acc[4], xB, w0); fma2(acc[5], xB, w1);
        fma2(acc[6], xB, w2); fma2(acc[7], xB, w3);
    }

    // unpack to hs
    #pragma unroll
    for (int j = 0; j < 4; j++) {
        int c = tx + 16 * j;
        float lo, hi;
        unpack2(acc[j], lo, hi);
        hs[(4*ty+0)*HS_STRIDE + c] = lo;
        hs[(4*ty+1)*HS_STRIDE + c] = hi;
        unpack2(acc[4+j], lo, hi);
        hs[(4*ty+2)*HS_STRIDE + c] = lo;
        hs[(4*ty+3)*HS_STRIDE + c] = hi;
    }
    __syncthreads();

    // coalesced h1 writes
    #pragma unroll
    for (int r = 0; r < 4; r++) {
        int idx = r * 128 + t;
        int node = idx >> 4, q = (idx & 15) * 4;
        float4 v = *(const float4*)(hs + node * HS_STRIDE + q);
        *(float4*)(d_h1 + (size_t)(base + node) * 64 + q) = v;
    }
    // per (node, head) logits + m1
    #pragma unroll
    for (int r = 0; r < 2; r++) {
        int u = r * 128 + t;
        int node = u >> 3, h = u & 7;
        const float* hp = hs + node * HS_STRIDE + h * 8;
        float als = 0.f, ald = 0.f;
        #pragma unroll
        for (int i = 0; i < 8; i++) {
            float hv = hp[i];
            als += hv * a_s[h * 8 + i];
            ald += hv * a_d[h * 8 + i];
        }
        int gi = (base + node) * 8 + h;
        d_als1[gi] = als;
        d_ald1[gi] = ald;
        d_m1[gi]   = lrelu(als + ald);
    }
}

// ---------------- kA1: layer-1 pull aggregation, 1 warp / node ---------------
__global__ void __launch_bounds__(256) kA1(const float* __restrict__ b1) {
    int d = (blockIdx.x * 256 + threadIdx.x) >> 5;
    int L = threadIdx.x & 31;
    int h8 = L & 7;

    float ald_d = d_ald1[d * 8 + h8];
    float m_d   = d_m1  [d * 8 + h8];
    float acc0 = d_h1[d * 64 + L];
    float acc1 = d_h1[d * 64 + 32 + L];
    float sumw = 1.f;

    int row = d_rowptr[d], end = d_rowptr[d + 1];
    for (int b = row; b < end; b += 32) {
        int cnt = min(32, end - b);
        int sreg = (b + L < end) ? d_esrc[b + L] : 0;
        for (int j = 0; j < cnt; j++) {
            int s = __shfl_sync(0xffffffffu, sreg, j);
            float a = d_als1[s * 8 + h8];
            float w = __expf(lrelu(a + ald_d) - m_d);
            float wA = __shfl_sync(0xffffffffu, w, L >> 3);
            float wB = __shfl_sync(0xffffffffu, w, 4 + (L >> 3));
            acc0 += wA * d_h1[s * 64 + L];
            acc1 += wB * d_h1[s * 64 + 32 + L];
            sumw += w;
        }
    }
    float sA = __shfl_sync(0xffffffffu, sumw, L >> 3);
    float sB = __shfl_sync(0xffffffffu, sumw, 4 + (L >> 3));
    float v0 = acc0 * (1.f / (sA + 1e-16f)) + b1[L];
    float v1 = acc1 * (1.f / (sB + 1e-16f)) + b1[32 + L];
    v0 = v0 > 0.f ? v0 : expm1f(v0);
    v1 = v1 > 0.f ? v1 : expm1f(v1);
    d_h2[d * 64 + L]      = v0;
    d_h2[d * 64 + 32 + L] = v1;
}

// ---------------- k5: g = h2 @ W2, layer-2 logits + m2 -----------------------
__global__ void __launch_bounds__(256) k5_prep2(
    const float* __restrict__ W2, const float* __restrict__ a_s2,
    const float* __restrict__ a_d2)
{
    __shared__ float W2s[HC * NCLASS];
    __shared__ float as2s[NCLASS], ad2s[NCLASS];
    int t = threadIdx.x;
    #pragma unroll
    for (int r = 0; r < 8; r++) W2s[r * 256 + t] = W2[r * 256 + t];
    if (t < NCLASS) { as2s[t] = a_s2[t]; ad2s[t] = a_d2[t]; }
    __syncthreads();

    int d = blockIdx.x * 8 + (t >> 5);
    int L = t & 31;
    float h0 = d_h2[d * 64 + L];
    float h1 = d_h2[d * 64 + 32 + L];
    float g = 0.f;
    #pragma unroll
    for (int k = 0; k < 32; k++)
        g += __shfl_sync(0xffffffffu, h0, k) * W2s[k * 32 + L];
    #pragma unroll
    for (int k = 0; k < 32; k++)
        g += __shfl_sync(0xffffffffu, h1, k) * W2s[(32 + k) * 32 + L];
    d_g[d * 32 + L] = g;

    float ps = g * as2s[L];
    float pd = g * ad2s[L];
    #pragma unroll
    for (int o = 16; o > 0; o >>= 1) {
        ps += __shfl_xor_sync(0xffffffffu, ps, o);
        pd += __shfl_xor_sync(0xffffffffu, pd, o);
    }
    if (L == 0) {
        d_als2[d] = ps;
        d_ald2[d] = pd;
        d_m2[d] = lrelu(ps + pd);
    }
}

// ---------------- kA2: layer-2 pull + fused log_softmax ----------------------
__global__ void __launch_bounds__(256) kA2(const float* __restrict__ b2,
                                           float* __restrict__ out) {
    int d = (blockIdx.x * 256 + threadIdx.x) >> 5;
    int L = threadIdx.x & 31;

    float ald = d_ald2[d];
    float m   = d_m2[d];
    float acc = d_g[d * 32 + L];
    float sumw = 1.f;

    int row = d_rowptr[d], end = d_rowptr[d + 1];
    for (int b = row; b < end; b += 32) {
        int cnt = min(32, end - b);
        int sreg = (b + L < end) ? d_esrc[b + L] : 0;
        for (int j = 0; j < cnt; j++) {
            int s = __shfl_sync(0xffffffffu, sreg, j);
            float w = __expf(lrelu(d_als2[s] + ald) - m);
            acc += w * d_g[s * 32 + L];
            sumw += w;
        }
    }
    float v = acc * (1.f / (sumw + 1e-16f)) + b2[L];
    float mx = v;
    #pragma unroll
    for (int o = 16; o > 0; o >>= 1) mx = fmaxf(mx, __shfl_xor_sync(0xffffffffu, mx, o));
    float se = __expf(v - mx);
    #pragma unroll
    for (int o = 16; o > 0; o >>= 1) se += __shfl_xor_sync(0xffffffffu, se, o);
    out[d * 32 + L] = v - mx - __logf(se);
}

// ---------------- launch ------------------------------------------------------
extern "C" void kernel_launch(void* const* d_in, const int* in_sizes, int n_in,
                              void* d_out, int out_size)
{
    const float* x   = (const float*)d_in[0];
    const void*  ei  = d_in[1];
    const float* W1  = (const float*)d_in[2];
    const float* as1 = (const float*)d_in[3];
    const float* ad1 = (const float*)d_in[4];
    const float* b1  = (const float*)d_in[5];
    const float* W2  = (const float*)d_in[6];
    const float* as2 = (const float*)d_in[7];
    const float* ad2 = (const float*)d_in[8];
    const float* b2  = (const float*)d_in[9];
    float* out = (float*)d_out;

    int E  = in_sizes[1] / 2;
    int nb = (N_NODES + 1023) / 1024;

    static int smem_set = 0;
    if (!smem_set) {
        cudaFuncSetAttribute(k1_gemm1, cudaFuncAttributeMaxDynamicSharedMemorySize, SMEM_K1);
        smem_set = 1;
    }

    k_detect<<<1, 1>>>(ei);
    k_zero  <<<(N_NODES + 255) / 256, 256>>>();
    k_conv  <<<(E + 255) / 256, 256>>>(ei, E);
    kscan1  <<<nb, 1024>>>(N_NODES);
    kscan2  <<<1, 128>>>(nb);
    kscan3  <<<(N_NODES + 256) / 256, 256>>>(E);
    k_scat  <<<(E + 255) / 256, 256>>>(E);
    k1_gemm1<<<N_NODES / 32, 128, SMEM_K1>>>(x, W1, as1, ad1);
    kA1     <<<N_NODES / 8, 256>>>(b1);
    k5_prep2<<<N_NODES / 8, 256>>>(W2, as2, ad2);
    kA2     <<<N_NODES / 8, 256>>>(b2, out);
}

// round 4
// speedup vs baseline: 2.1998x; 1.0276x over previous
#include <cuda_runtime.h>
#include <math.h>

#define N_NODES 100000
#define NFEAT   256
#define HEADS   8
#define HC      64
#define NCLASS  32
#define NEG     0.2f
#define MAX_E   1700000

typedef unsigned long long ull;

// ---------------- scratch ----------------
__device__ float d_h1  [N_NODES * HC];
__device__ float d_h2  [N_NODES * HC];
__device__ float d_als1[N_NODES * HEADS];
__device__ float d_ald1[N_NODES * HEADS];
__device__ float d_m1  [N_NODES * HEADS];
__device__ float d_g   [N_NODES * NCLASS];
__device__ float d_als2[N_NODES];
__device__ float d_ald2[N_NODES];
__device__ float d_m2  [N_NODES];
__device__ int2  d_edge[MAX_E];
__device__ int   d_esrc[MAX_E + 32];
__device__ int   d_deg [N_NODES];
__device__ int   d_rowptr[N_NODES + 1];
__device__ int   d_cursor[N_NODES + 1];
__device__ int   d_bsum[128];
__device__ int   d_is64;

__device__ __forceinline__ float lrelu(float x){ return x >= 0.f ? x : NEG * x; }

__device__ __forceinline__ void fma2(ull& d, ull a, ull b){
    asm("fma.rn.f32x2 %0, %1, %2, %0;" : "+l"(d) : "l"(a), "l"(b));
}
__device__ __forceinline__ void unpack2(ull v, float& lo, float& hi){
    asm("mov.b64 {%0, %1}, %2;" : "=f"(lo), "=f"(hi) : "l"(v));
}

// ---------------- edge-index prep + CSR build ----------------
__global__ void k_detect(const void* ei) {
    const int* p = (const int*)ei;
    d_is64 = (p[1] == 0 && p[3] == 0 && p[5] == 0 && p[7] == 0) ? 1 : 0;
}

__global__ void k_zero() {
    int i = blockIdx.x * blockDim.x + threadIdx.x;
    if (i < N_NODES) d_deg[i] = 0;
}

__global__ void k_conv(const void* __restrict__ ei, int E) {
    int e = blockIdx.x * blockDim.x + threadIdx.x;
    if (e >= E) return;
    int s, d;
    if (d_is64) {
        const long long* p = (const long long*)ei;
        s = (int)p[e]; d = (int)p[E + e];
    } else {
        const int* p = (const int*)ei;
        s = p[e]; d = p[E + e];
    }
    d_edge[e] = make_int2(s, d);
    atomicAdd(&d_deg[d], 1);
}

__global__ void __launch_bounds__(1024) kscan1(int nElem) {
    __shared__ int wsum[32], wbase[32];
    int i = blockIdx.x * 1024 + threadIdx.x;
    int v = (i < nElem) ? d_deg[i] : 0;
    int lane = threadIdx.x & 31, w = threadIdx.x >> 5;
    int incl = v;
    #pragma unroll
    for (int o = 1; o < 32; o <<= 1) {
        int t = __shfl_up_sync(0xffffffffu, incl, o);
        if (lane >= o) incl += t;
    }
    if (lane == 31) wsum[w] = incl;
    __syncthreads();
    if (w == 0) {
        int s = wsum[lane], si = s;
        #pragma unroll
        for (int o = 1; o < 32; o <<= 1) {
            int t = __shfl_up_sync(0xffffffffu, si, o);
            if (lane >= o) si += t;
        }
        wbase[lane] = si - s;
    }
    __syncthreads();
    int excl = incl - v + wbase[w];
    if (i < nElem) d_rowptr[i] = excl;
    if (threadIdx.x == 1023) d_bsum[blockIdx.x] = excl + v;
}

__global__ void kscan2(int nb) {
    __shared__ int sm[128];
    int t = threadIdx.x;
    int v = (t < nb) ? d_bsum[t] : 0;
    sm[t] = v;
    __syncthreads();
    for (int o = 1; o < 128; o <<= 1) {
        int tmp = (t >= o) ? sm[t - o] : 0;
        __syncthreads();
        sm[t] += tmp;
        __syncthreads();
    }
    if (t < nb) d_bsum[t] = sm[t] - v;
}

__global__ void kscan3(int E) {
    int i = blockIdx.x * blockDim.x + threadIdx.x;
    if (i < N_NODES) {
        int r = d_rowptr[i] + d_bsum[i >> 10];
        d_rowptr[i] = r;
        d_cursor[i] = r;
    } else if (i == N_NODES) {
        d_rowptr[N_NODES] = E;
    }
}

__global__ void k_scat(int E) {
    int e = blockIdx.x * blockDim.x + threadIdx.x;
    if (e >= E) return;
    int2 ed = d_edge[e];
    int pos = atomicAdd(&d_cursor[ed.y], 1);
    d_esrc[pos] = ed.x;
}

// ---------------- K1: h1 = x @ W1 via even/odd-k f32x2 split -----------------
// 128 threads, tile 32 nodes x 64 cols. tn=t>>4 -> nodes 4tn..4tn+3,
// tc=t&15 -> cols tc+16j. acc[n][c] f32x2: lo=even-k partial, hi=odd-k.
#define XS_STR 260
#define WS_STR 258
#define HS_STR 68
#define SMEM_K1 ((32 * XS_STR + 64 * WS_STR) * 4)

__global__ void __launch_bounds__(128) k1_gemm1(
    const float* __restrict__ x, const float* __restrict__ W1,
    const float* __restrict__ a_s, const float* __restrict__ a_d)
{
    extern __shared__ float smem[];
    float* xs = smem;                 // [32][260] node-major, k contiguous
    float* ws = smem + 32 * XS_STR;   // [64][258] col-major, k contiguous
    float* hs = smem;                 // reused after compute: [32][68]

    int t = threadIdx.x;
    int base = blockIdx.x * 32;

    // load x tile: natural row layout
    #pragma unroll
    for (int r = 0; r < 16; r++) {
        int idx = r * 128 + t;        // float4 index, 2048 total
        int n = idx >> 6, q = idx & 63;
        float4 v = *(const float4*)(x + (size_t)(base + n) * NFEAT + q * 4);
        *(float4*)(xs + n * XS_STR + q * 4) = v;
    }
    // load W1 transposed: ws[c][k] = W1[k][c]
    #pragma unroll
    for (int r = 0; r < 32; r++) {
        int idx4 = r * 128 + t;       // 4096 float4s
        int k = idx4 >> 4, c4 = (idx4 & 15) * 4;
        float4 wv = ((const float4*)W1)[idx4];
        ws[(c4 + 0) * WS_STR + k] = wv.x;
        ws[(c4 + 1) * WS_STR + k] = wv.y;
        ws[(c4 + 2) * WS_STR + k] = wv.z;
        ws[(c4 + 3) * WS_STR + k] = wv.w;
    }
    __syncthreads();

    int tc = t & 15, tn = t >> 4;
    ull acc[4][4];
    #pragma unroll
    for (int i = 0; i < 4; i++)
        #pragma unroll
        for (int j = 0; j < 4; j++) acc[i][j] = 0;

    #pragma unroll 4
    for (int kp = 0; kp < NFEAT / 2; kp++) {
        ull xv[4], wv[4];
        #pragma unroll
        for (int i = 0; i < 4; i++)
            xv[i] = *(const ull*)(xs + (4 * tn + i) * XS_STR + 2 * kp);
        #pragma unroll
        for (int j = 0; j < 4; j++)
            wv[j] = *(const ull*)(ws + (tc + 16 * j) * WS_STR + 2 * kp);
        #pragma unroll
        for (int i = 0; i < 4; i++)
            #pragma unroll
            for (int j = 0; j < 4; j++)
                fma2(acc[i][j], xv[i], wv[j]);
    }
    __syncthreads();

    #pragma unroll
    for (int i = 0; i < 4; i++)
        #pragma unroll
        for (int j = 0; j < 4; j++) {
            float lo, hi; unpack2(acc[i][j], lo, hi);
            hs[(4 * tn + i) * HS_STR + tc + 16 * j] = lo + hi;
        }
    __syncthreads();

    // coalesced h1 writes
    #pragma unroll
    for (int r = 0; r < 4; r++) {
        int idx = r * 128 + t;
        int node = idx >> 4, q = (idx & 15) * 4;
        float4 v = *(const float4*)(hs + node * HS_STR + q);
        *(float4*)(d_h1 + (size_t)(base + node) * 64 + q) = v;
    }
    // per (node, head) logits + m1
    #pragma unroll
    for (int r = 0; r < 2; r++) {
        int u = r * 128 + t;
        int node = u >> 3, h = u & 7;
        const float* hp = hs + node * HS_STR + h * 8;
        float als = 0.f, ald = 0.f;
        #pragma unroll
        for (int i = 0; i < 8; i++) {
            float hv = hp[i];
            als += hv * a_s[h * 8 + i];
            ald += hv * a_d[h * 8 + i];
        }
        int gi = (base + node) * 8 + h;
        d_als1[gi] = als;
        d_ald1[gi] = ald;
        d_m1[gi]   = lrelu(als + ald);
    }
}

// ---------------- kA1: layer-1 pull, two-phase, 1 warp / node ----------------
__global__ void __launch_bounds__(256) kA1(const float* __restrict__ b1) {
    __shared__ float wsh[8][8 * 34 + 2];   // per warp: [head][j 0..31, 32=sum]
    int warp = threadIdx.x >> 5;
    int d = blockIdx.x * 8 + warp;
    int L = threadIdx.x & 31;
    float* wsm = &wsh[warp][0];

    float4 aldA = *(const float4*)(d_ald1 + d * 8);
    float4 aldB = *(const float4*)(d_ald1 + d * 8 + 4);
    float4 mA   = *(const float4*)(d_m1   + d * 8);
    float4 mB   = *(const float4*)(d_m1   + d * 8 + 4);

    float sw[8];
    #pragma unroll
    for (int h = 0; h < 8; h++) sw[h] = 0.f;

    float acc0 = d_h1[d * 64 + L];
    float acc1 = d_h1[d * 64 + 32 + L];

    int row = d_rowptr[d], end = d_rowptr[d + 1];
    for (int b = row; b < end; b += 32) {
        int cnt = min(32, end - b);
        int sreg = (b + L < end) ? d_esrc[b + L] : -1;
        // phase A: each lane computes 8 head-weights for its own edge
        if (sreg >= 0) {
            float4 asA = *(const float4*)(d_als1 + sreg * 8);
            float4 asB = *(const float4*)(d_als1 + sreg * 8 + 4);
            float w0 = __expf(lrelu(asA.x + aldA.x) - mA.x);
            float w1 = __expf(lrelu(asA.y + aldA.y) - mA.y);
            float w2 = __expf(lrelu(asA.z + aldA.z) - mA.z);
            float w3 = __expf(lrelu(asA.w + aldA.w) - mA.w);
            float w4 = __expf(lrelu(asB.x + aldB.x) - mB.x);
            float w5 = __expf(lrelu(asB.y + aldB.y) - mB.y);
            float w6 = __expf(lrelu(asB.z + aldB.z) - mB.z);
            float w7 = __expf(lrelu(asB.w + aldB.w) - mB.w);
            sw[0] += w0; sw[1] += w1; sw[2] += w2; sw[3] += w3;
            sw[4] += w4; sw[5] += w5; sw[6] += w6; sw[7] += w7;
            wsm[0 * 34 + L] = w0; wsm[1 * 34 + L] = w1;
            wsm[2 * 34 + L] = w2; wsm[3 * 34 + L] = w3;
            wsm[4 * 34 + L] = w4; wsm[5 * 34 + L] = w5;
            wsm[6 * 34 + L] = w6; wsm[7 * 34 + L] = w7;
        }
        __syncwarp();
        // phase B: light accumulation, loads independent across j
        int hA = (L >> 3) * 34, hB = (4 + (L >> 3)) * 34;
        #pragma unroll 4
        for (int j = 0; j < cnt; j++) {
            int s = __shfl_sync(0xffffffffu, sreg, j);
            float wA = wsm[hA + j];
            float wB = wsm[hB + j];
            acc0 += wA * d_h1[s * 64 + L];
            acc1 += wB * d_h1[s * 64 + 32 + L];
        }
        __syncwarp();
    }
    // butterfly-reduce denominators
    #pragma unroll
    for (int h = 0; h < 8; h++) {
        #pragma unroll
        for (int o = 16; o > 0; o >>= 1)
            sw[h] += __shfl_xor_sync(0xffffffffu, sw[h], o);
    }
    if (L < 8) wsm[L * 34 + 32] = sw[L] + 1.f;   // + self term
    __syncwarp();
    float sA = wsm[(L >> 3) * 34 + 32];
    float sB = wsm[(4 + (L >> 3)) * 34 + 32];

    float v0 = acc0 * (1.f / (sA + 1e-16f)) + b1[L];
    float v1 = acc1 * (1.f / (sB + 1e-16f)) + b1[32 + L];
    v0 = v0 > 0.f ? v0 : expm1f(v0);
    v1 = v1 > 0.f ? v1 : expm1f(v1);
    d_h2[d * 64 + L]      = v0;
    d_h2[d * 64 + 32 + L] = v1;
}

// ---------------- k5: g = h2 @ W2, layer-2 logits + m2 -----------------------
__global__ void __launch_bounds__(256) k5_prep2(
    const float* __restrict__ W2, const float* __restrict__ a_s2,
    const float* __restrict__ a_d2)
{
    __shared__ float W2s[HC * NCLASS];
    __shared__ float as2s[NCLASS], ad2s[NCLASS];
    int t = threadIdx.x;
    #pragma unroll
    for (int r = 0; r < 8; r++) W2s[r * 256 + t] = W2[r * 256 + t];
    if (t < NCLASS) { as2s[t] = a_s2[t]; ad2s[t] = a_d2[t]; }
    __syncthreads();

    int d = blockIdx.x * 8 + (t >> 5);
    int L = t & 31;
    float h0 = d_h2[d * 64 + L];
    float h1 = d_h2[d * 64 + 32 + L];
    float g = 0.f;
    #pragma unroll
    for (int k = 0; k < 32; k++)
        g += __shfl_sync(0xffffffffu, h0, k) * W2s[k * 32 + L];
    #pragma unroll
    for (int k = 0; k < 32; k++)
        g += __shfl_sync(0xffffffffu, h1, k) * W2s[(32 + k) * 32 + L];
    d_g[d * 32 + L] = g;

    float ps = g * as2s[L];
    float pd = g * ad2s[L];
    #pragma unroll
    for (int o = 16; o > 0; o >>= 1) {
        ps += __shfl_xor_sync(0xffffffffu, ps, o);
        pd += __shfl_xor_sync(0xffffffffu, pd, o);
    }
    if (L == 0) {
        d_als2[d] = ps;
        d_ald2[d] = pd;
        d_m2[d] = lrelu(ps + pd);
    }
}

// ---------------- kA2: layer-2 pull, two-phase + fused log_softmax -----------
__global__ void __launch_bounds__(256) kA2(const float* __restrict__ b2,
                                           float* __restrict__ out) {
    int d = (blockIdx.x * 256 + threadIdx.x) >> 5;
    int L = threadIdx.x & 31;

    float ald = d_ald2[d];
    float m   = d_m2[d];
    float acc = d_g[d * 32 + L];
    float swsum = 0.f;

    int row = d_rowptr[d], end = d_rowptr[d + 1];
    for (int b = row; b < end; b += 32) {
        int cnt = min(32, end - b);
        int sreg = (b + L < end) ? d_esrc[b + L] : -1;
        float w = 0.f;
        if (sreg >= 0) w = __expf(lrelu(d_als2[sreg] + ald) - m);
        swsum += w;
        #pragma unroll 4
        for (int j = 0; j < cnt; j++) {
            int s  = __shfl_sync(0xffffffffu, sreg, j);
            float wj = __shfl_sync(0xffffffffu, w, j);
            acc += wj * d_g[s * 32 + L];
        }
    }
    #pragma unroll
    for (int o = 16; o > 0; o >>= 1)
        swsum += __shfl_xor_sync(0xffffffffu, swsum, o);

    float v = acc * (1.f / (swsum + 1.f + 1e-16f)) + b2[L];
    float mx = v;
    #pragma unroll
    for (int o = 16; o > 0; o >>= 1) mx = fmaxf(mx, __shfl_xor_sync(0xffffffffu, mx, o));
    float se = __expf(v - mx);
    #pragma unroll
    for (int o = 16; o > 0; o >>= 1) se += __shfl_xor_sync(0xffffffffu, se, o);
    out[d * 32 + L] = v - mx - __logf(se);
}

// ---------------- launch ------------------------------------------------------
extern "C" void kernel_launch(void* const* d_in, const int* in_sizes, int n_in,
                              void* d_out, int out_size)
{
    const float* x   = (const float*)d_in[0];
    const void*  ei  = d_in[1];
    const float* W1  = (const float*)d_in[2];
    const float* as1 = (const float*)d_in[3];
    const float* ad1 = (const float*)d_in[4];
    const float* b1  = (const float*)d_in[5];
    const float* W2  = (const float*)d_in[6];
    const float* as2 = (const float*)d_in[7];
    const float* ad2 = (const float*)d_in[8];
    const float* b2  = (const float*)d_in[9];
    float* out = (float*)d_out;

    int E  = in_sizes[1] / 2;
    int nb = (N_NODES + 1023) / 1024;

    static int smem_set = 0;
    if (!smem_set) {
        cudaFuncSetAttribute(k1_gemm1, cudaFuncAttributeMaxDynamicSharedMemorySize, SMEM_K1);
        smem_set = 1;
    }

    k_detect<<<1, 1>>>(ei);
    k_zero  <<<(N_NODES + 255) / 256, 256>>>();
    k_conv  <<<(E + 255) / 256, 256>>>(ei, E);
    k1_gemm1<<<N_NODES / 32, 128, SMEM_K1>>>(x, W1, as1, ad1);   // profiled launch
    kscan1  <<<nb, 1024>>>(N_NODES);
    kscan2  <<<1, 128>>>(nb);
    kscan3  <<<(N_NODES + 256) / 256, 256>>>(E);
    k_scat  <<<(E + 255) / 256, 256>>>(E);
    kA1     <<<N_NODES / 8, 256>>>(b1);
    k5_prep2<<<N_NODES / 8, 256>>>(W2, as2, ad2);
    kA2     <<<N_NODES / 8, 256>>>(b2, out);
}

// round 5
// speedup vs baseline: 2.3016x; 1.0463x over previous
#include <cuda_runtime.h>
#include <math.h>

#define N_NODES 100000
#define NFEAT   256
#define HEADS   8
#define HC      64
#define NCLASS  32
#define NEG     0.2f
#define MAX_E   1700000

typedef unsigned long long ull;

// ---------------- scratch ----------------
__device__ float d_h1  [N_NODES * HC];
__device__ float d_h2  [N_NODES * HC];
__device__ float d_als1[N_NODES * HEADS];
__device__ float d_ald1[N_NODES * HEADS];
__device__ float d_m1  [N_NODES * HEADS];
__device__ float d_g   [N_NODES * NCLASS];
__device__ float d_als2[N_NODES];
__device__ float d_ald2[N_NODES];
__device__ float d_m2  [N_NODES];
__device__ int2  d_edge[MAX_E];
__device__ int   d_esrc[MAX_E + 32];
__device__ int   d_deg [N_NODES];
__device__ int   d_rowptr[N_NODES + 1];
__device__ int   d_cursor[N_NODES + 1];
__device__ int   d_bsum[128];
__device__ int   d_is64;

__device__ __forceinline__ float lrelu(float x){ return x >= 0.f ? x : NEG * x; }

// FMA-only exp: exp(x) = 2^(x*log2e), round-to-int via magic constant,
// degree-5 poly on [-0.5,0.5], exponent spliced via int add. ~2e-6 rel err.
__device__ __forceinline__ float fexp(float x) {
    x = fmaxf(x, -80.f);
    float t = x * 1.442695041f;
    float z = t + 12582912.f;                 // 2^23 + 2^22
    int   n = __float_as_int(z) - 0x4B400000; // round(t)
    float f = t - (z - 12582912.f);           // [-0.5, 0.5]
    float p = 1.3333558e-3f;
    p = fmaf(p, f, 9.6181291e-3f);
    p = fmaf(p, f, 5.5504109e-2f);
    p = fmaf(p, f, 2.4022651e-1f);
    p = fmaf(p, f, 6.9314718e-1f);
    p = fmaf(p, f, 1.0f);
    return p * __int_as_float((n << 23) + 0x3F800000);
}

__device__ __forceinline__ void fma2(ull& d, ull a, ull b){
    asm("fma.rn.f32x2 %0, %1, %2, %0;" : "+l"(d) : "l"(a), "l"(b));
}
__device__ __forceinline__ void unpack2(ull v, float& lo, float& hi){
    asm("mov.b64 {%0, %1}, %2;" : "=f"(lo), "=f"(hi) : "l"(v));
}

// ---------------- edge-index prep + CSR build ----------------
__global__ void k_detect(const void* ei) {
    const int* p = (const int*)ei;
    d_is64 = (p[1] == 0 && p[3] == 0 && p[5] == 0 && p[7] == 0) ? 1 : 0;
}

__global__ void k_zero() {
    int i = blockIdx.x * blockDim.x + threadIdx.x;
    if (i < N_NODES) d_deg[i] = 0;
}

__global__ void k_conv(const void* __restrict__ ei, int E) {
    int e = blockIdx.x * blockDim.x + threadIdx.x;
    if (e >= E) return;
    int s, d;
    if (d_is64) {
        const long long* p = (const long long*)ei;
        s = (int)p[e]; d = (int)p[E + e];
    } else {
        const int* p = (const int*)ei;
        s = p[e]; d = p[E + e];
    }
    d_edge[e] = make_int2(s, d);
    atomicAdd(&d_deg[d], 1);
}

__global__ void __launch_bounds__(1024) kscan1(int nElem) {
    __shared__ int wsum[32], wbase[32];
    int i = blockIdx.x * 1024 + threadIdx.x;
    int v = (i < nElem) ? d_deg[i] : 0;
    int lane = threadIdx.x & 31, w = threadIdx.x >> 5;
    int incl = v;
    #pragma unroll
    for (int o = 1; o < 32; o <<= 1) {
        int t = __shfl_up_sync(0xffffffffu, incl, o);
        if (lane >= o) incl += t;
    }
    if (lane == 31) wsum[w] = incl;
    __syncthreads();
    if (w == 0) {
        int s = wsum[lane], si = s;
        #pragma unroll
        for (int o = 1; o < 32; o <<= 1) {
            int t = __shfl_up_sync(0xffffffffu, si, o);
            if (lane >= o) si += t;
        }
        wbase[lane] = si - s;
    }
    __syncthreads();
    int excl = incl - v + wbase[w];
    if (i < nElem) d_rowptr[i] = excl;
    if (threadIdx.x == 1023) d_bsum[blockIdx.x] = excl + v;
}

__global__ void kscan2(int nb) {
    __shared__ int sm[128];
    int t = threadIdx.x;
    int v = (t < nb) ? d_bsum[t] : 0;
    sm[t] = v;
    __syncthreads();
    for (int o = 1; o < 128; o <<= 1) {
        int tmp = (t >= o) ? sm[t - o] : 0;
        __syncthreads();
        sm[t] += tmp;
        __syncthreads();
    }
    if (t < nb) d_bsum[t] = sm[t] - v;
}

__global__ void kscan3(int E) {
    int i = blockIdx.x * blockDim.x + threadIdx.x;
    if (i < N_NODES) {
        int r = d_rowptr[i] + d_bsum[i >> 10];
        d_rowptr[i] = r;
        d_cursor[i] = r;
    } else if (i == N_NODES) {
        d_rowptr[N_NODES] = E;
    }
}

__global__ void k_scat(int E) {
    int e = blockIdx.x * blockDim.x + threadIdx.x;
    if (e >= E) return;
    int2 ed = d_edge[e];
    int pos = atomicAdd(&d_cursor[ed.y], 1);
    d_esrc[pos] = ed.x;
}

// ---------------- K1: h1 = x @ W1, double-buffered, even/odd f32x2 -----------
// 256 threads, tile 64 nodes x 64 cols, K chunks of 16, thread = 4 nodes x 4 cols.
#define WS_ST 18
#define HS_ST 68

__global__ void __launch_bounds__(256) k1_gemm1(
    const float* __restrict__ x, const float* __restrict__ W1,
    const float* __restrict__ a_s, const float* __restrict__ a_d)
{
    __shared__ float sm[4352];
    float* xs = sm;              // [2][64*16]
    float* ws = sm + 2048;       // [2][64*18]  col-major, k contiguous, pad 18
    float* hs = sm;              // reused epilogue: [64][68]

    int t = threadIdx.x;
    int base = blockIdx.x * 64;
    int tx = t & 15, ty = t >> 4;

    // staging roles
    int xnode = t >> 2, xq = t & 3;
    int gx = min(base + xnode, N_NODES - 1);
    const float4* xsrc = (const float4*)(x + (size_t)gx * NFEAT);
    int wr = t >> 4, wc4 = (t & 15) * 4;

    float4 xv = xsrc[xq];
    float4 wv = *(const float4*)(W1 + wr * 64 + wc4);

    ull acc[4][4];
    #pragma unroll
    for (int i = 0; i < 4; i++)
        #pragma unroll
        for (int j = 0; j < 4; j++) acc[i][j] = 0;

    // store chunk 0
    *(float4*)(xs + xnode * 16 + xq * 4) = xv;
    ws[(wc4 + 0) * WS_ST + wr] = wv.x;
    ws[(wc4 + 1) * WS_ST + wr] = wv.y;
    ws[(wc4 + 2) * WS_ST + wr] = wv.z;
    ws[(wc4 + 3) * WS_ST + wr] = wv.w;
    __syncthreads();

    for (int c = 0; c < 16; c++) {
        int cur = (c & 1) ? 1 : 0;
        float* xb = xs + cur * 1024;
        float* wb = ws + cur * 1152;
        if (c < 15) {
            xv = xsrc[(c + 1) * 4 + xq];
            wv = *(const float4*)(W1 + ((c + 1) * 16 + wr) * 64 + wc4);
        }
        #pragma unroll
        for (int kp = 0; kp < 8; kp++) {
            ull xr[4], wr2[4];
            #pragma unroll
            for (int i = 0; i < 4; i++)
                xr[i] = *(const ull*)(xb + (4 * ty + i) * 16 + 2 * kp);
            #pragma unroll
            for (int j = 0; j < 4; j++)
                wr2[j] = *(const ull*)(wb + (tx + 16 * j) * WS_ST + 2 * kp);
            #pragma unroll
            for (int i = 0; i < 4; i++)
                #pragma unroll
                for (int j = 0; j < 4; j++)
                    fma2(acc[i][j], xr[i], wr2[j]);
        }
        if (c < 15) {
            int nxt = 1 - cur;
            float* xb2 = xs + nxt * 1024;
            float* wb2 = ws + nxt * 1152;
            *(float4*)(xb2 + xnode * 16 + xq * 4) = xv;
            wb2[(wc4 + 0) * WS_ST + wr] = wv.x;
            wb2[(wc4 + 1) * WS_ST + wr] = wv.y;
            wb2[(wc4 + 2) * WS_ST + wr] = wv.z;
            wb2[(wc4 + 3) * WS_ST + wr] = wv.w;
        }
        __syncthreads();
    }

    // epilogue: results to smem (reuses xs/ws region)
    #pragma unroll
    for (int i = 0; i < 4; i++)
        #pragma unroll
        for (int j = 0; j < 4; j++) {
            float lo, hi; unpack2(acc[i][j], lo, hi);
            hs[(4 * ty + i) * HS_ST + tx + 16 * j] = lo + hi;
        }
    __syncthreads();

    // coalesced h1 writes
    #pragma unroll
    for (int r = 0; r < 4; r++) {
        int idx = r * 256 + t;
        int node = idx >> 4, q = (idx & 15) * 4;
        if (base + node < N_NODES) {
            float4 v = *(const float4*)(hs + node * HS_ST + q);
            *(float4*)(d_h1 + (size_t)(base + node) * 64 + q) = v;
        }
    }
    // per (node, head) logits + m1
    #pragma unroll
    for (int r = 0; r < 2; r++) {
        int u = r * 256 + t;
        int node = u >> 3, h = u & 7;
        if (base + node < N_NODES) {
            const float* hp = hs + node * HS_ST + h * 8;
            float als = 0.f, ald = 0.f;
            #pragma unroll
            for (int i = 0; i < 8; i++) {
                float hv = hp[i];
                als += hv * a_s[h * 8 + i];
                ald += hv * a_d[h * 8 + i];
            }
            int gi = (base + node) * 8 + h;
            d_als1[gi] = als;
            d_ald1[gi] = ald;
            d_m1[gi]   = lrelu(als + ald);
        }
    }
}

// ---------------- kA1: layer-1 pull, two-phase, poly exp, 1 warp / node ------
__global__ void __launch_bounds__(256) kA1(const float* __restrict__ b1) {
    __shared__ float wsh[8][8 * 34 + 2];
    int warp = threadIdx.x >> 5;
    int d = blockIdx.x * 8 + warp;
    int L = threadIdx.x & 31;
    float* wsm = &wsh[warp][0];

    float4 aldA = *(const float4*)(d_ald1 + d * 8);
    float4 aldB = *(const float4*)(d_ald1 + d * 8 + 4);
    float4 mA   = *(const float4*)(d_m1   + d * 8);
    float4 mB   = *(const float4*)(d_m1   + d * 8 + 4);

    float sw[8];
    #pragma unroll
    for (int h = 0; h < 8; h++) sw[h] = 0.f;

    float acc0 = d_h1[d * 64 + L];
    float acc1 = d_h1[d * 64 + 32 + L];

    int row = d_rowptr[d], end = d_rowptr[d + 1];
    for (int b = row; b < end; b += 32) {
        int cnt = min(32, end - b);
        int sreg = (b + L < end) ? d_esrc[b + L] : -1;
        if (sreg >= 0) {
            float4 asA = *(const float4*)(d_als1 + sreg * 8);
            float4 asB = *(const float4*)(d_als1 + sreg * 8 + 4);
            float w0 = fexp(lrelu(asA.x + aldA.x) - mA.x);
            float w1 = fexp(lrelu(asA.y + aldA.y) - mA.y);
            float w2 = fexp(lrelu(asA.z + aldA.z) - mA.z);
            float w3 = fexp(lrelu(asA.w + aldA.w) - mA.w);
            float w4 = fexp(lrelu(asB.x + aldB.x) - mB.x);
            float w5 = fexp(lrelu(asB.y + aldB.y) - mB.y);
            float w6 = fexp(lrelu(asB.z + aldB.z) - mB.z);
            float w7 = fexp(lrelu(asB.w + aldB.w) - mB.w);
            sw[0] += w0; sw[1] += w1; sw[2] += w2; sw[3] += w3;
            sw[4] += w4; sw[5] += w5; sw[6] += w6; sw[7] += w7;
            wsm[0 * 34 + L] = w0; wsm[1 * 34 + L] = w1;
            wsm[2 * 34 + L] = w2; wsm[3 * 34 + L] = w3;
            wsm[4 * 34 + L] = w4; wsm[5 * 34 + L] = w5;
            wsm[6 * 34 + L] = w6; wsm[7 * 34 + L] = w7;
        }
        __syncwarp();
        int hA = (L >> 3) * 34, hB = (4 + (L >> 3)) * 34;
        #pragma unroll 4
        for (int j = 0; j < cnt; j++) {
            int s = __shfl_sync(0xffffffffu, sreg, j);
            float wA = wsm[hA + j];
            float wB = wsm[hB + j];
            acc0 += wA * d_h1[s * 64 + L];
            acc1 += wB * d_h1[s * 64 + 32 + L];
        }
        __syncwarp();
    }
    #pragma unroll
    for (int h = 0; h < 8; h++) {
        #pragma unroll
        for (int o = 16; o > 0; o >>= 1)
            sw[h] += __shfl_xor_sync(0xffffffffu, sw[h], o);
    }
    if (L < 8) wsm[L * 34 + 32] = sw[L] + 1.f;   // + self term
    __syncwarp();
    float sA = wsm[(L >> 3) * 34 + 32];
    float sB = wsm[(4 + (L >> 3)) * 34 + 32];

    float v0 = acc0 * (1.f / (sA + 1e-16f)) + b1[L];
    float v1 = acc1 * (1.f / (sB + 1e-16f)) + b1[32 + L];
    v0 = v0 > 0.f ? v0 : fexp(v0) - 1.f;   // ELU
    v1 = v1 > 0.f ? v1 : fexp(v1) - 1.f;
    d_h2[d * 64 + L]      = v0;
    d_h2[d * 64 + 32 + L] = v1;
}

// ---------------- k5: g = h2 @ W2, layer-2 logits + m2 -----------------------
__global__ void __launch_bounds__(256) k5_prep2(
    const float* __restrict__ W2, const float* __restrict__ a_s2,
    const float* __restrict__ a_d2)
{
    __shared__ float W2s[HC * NCLASS];
    __shared__ float as2s[NCLASS], ad2s[NCLASS];
    int t = threadIdx.x;
    #pragma unroll
    for (int r = 0; r < 8; r++) W2s[r * 256 + t] = W2[r * 256 + t];
    if (t < NCLASS) { as2s[t] = a_s2[t]; ad2s[t] = a_d2[t]; }
    __syncthreads();

    int d = blockIdx.x * 8 + (t >> 5);
    int L = t & 31;
    float h0 = d_h2[d * 64 + L];
    float h1 = d_h2[d * 64 + 32 + L];
    float g = 0.f;
    #pragma unroll
    for (int k = 0; k < 32; k++)
        g += __shfl_sync(0xffffffffu, h0, k) * W2s[k * 32 + L];
    #pragma unroll
    for (int k = 0; k < 32; k++)
        g += __shfl_sync(0xffffffffu, h1, k) * W2s[(32 + k) * 32 + L];
    d_g[d * 32 + L] = g;

    float ps = g * as2s[L];
    float pd = g * ad2s[L];
    #pragma unroll
    for (int o = 16; o > 0; o >>= 1) {
        ps += __shfl_xor_sync(0xffffffffu, ps, o);
        pd += __shfl_xor_sync(0xffffffffu, pd, o);
    }
    if (L == 0) {
        d_als2[d] = ps;
        d_ald2[d] = pd;
        d_m2[d] = lrelu(ps + pd);
    }
}

// ---------------- kA2: layer-2 pull + fused log_softmax ----------------------
__global__ void __launch_bounds__(256) kA2(const float* __restrict__ b2,
                                           float* __restrict__ out) {
    int d = (blockIdx.x * 256 + threadIdx.x) >> 5;
    int L = threadIdx.x & 31;

    float ald = d_ald2[d];
    float m   = d_m2[d];
    float acc = d_g[d * 32 + L];
    float swsum = 0.f;

    int row = d_rowptr[d], end = d_rowptr[d + 1];
    for (int b = row; b < end; b += 32) {
        int cnt = min(32, end - b);
        int sreg = (b + L < end) ? d_esrc[b + L] : -1;
        float w = 0.f;
        if (sreg >= 0) w = fexp(lrelu(d_als2[sreg] + ald) - m);
        swsum += w;
        #pragma unroll 4
        for (int j = 0; j < cnt; j++) {
            int s  = __shfl_sync(0xffffffffu, sreg, j);
            float wj = __shfl_sync(0xffffffffu, w, j);
            acc += wj * d_g[s * 32 + L];
        }
    }
    #pragma unroll
    for (int o = 16; o > 0; o >>= 1)
        swsum += __shfl_xor_sync(0xffffffffu, swsum, o);

    float v = acc * (1.f / (swsum + 1.f + 1e-16f)) + b2[L];
    float mx = v;
    #pragma unroll
    for (int o = 16; o > 0; o >>= 1) mx = fmaxf(mx, __shfl_xor_sync(0xffffffffu, mx, o));
    float se = __expf(v - mx);
    #pragma unroll
    for (int o = 16; o > 0; o >>= 1) se += __shfl_xor_sync(0xffffffffu, se, o);
    out[d * 32 + L] = v - mx - __logf(se);
}

// ---------------- launch ------------------------------------------------------
extern "C" void kernel_launch(void* const* d_in, const int* in_sizes, int n_in,
                              void* d_out, int out_size)
{
    const float* x   = (const float*)d_in[0];
    const void*  ei  = d_in[1];
    const float* W1  = (const float*)d_in[2];
    const float* as1 = (const float*)d_in[3];
    const float* ad1 = (const float*)d_in[4];
    const float* b1  = (const float*)d_in[5];
    const float* W2  = (const float*)d_in[6];
    const float* as2 = (const float*)d_in[7];
    const float* ad2 = (const float*)d_in[8];
    const float* b2  = (const float*)d_in[9];
    float* out = (float*)d_out;

    int E  = in_sizes[1] / 2;
    int nb = (N_NODES + 1023) / 1024;

    k_detect<<<1, 1>>>(ei);
    k_zero  <<<(N_NODES + 255) / 256, 256>>>();
    k_conv  <<<(E + 255) / 256, 256>>>(ei, E);
    k1_gemm1<<<(N_NODES + 63) / 64, 256>>>(x, W1, as1, ad1);   // profiled slot
    kscan1  <<<nb, 1024>>>(N_NODES);
    kscan2  <<<1, 128>>>(nb);
    kscan3  <<<(N_NODES + 256) / 256, 256>>>(E);
    k_scat  <<<(E + 255) / 256, 256>>>(E);
    kA1     <<<N_NODES / 8, 256>>>(b1);
    k5_prep2<<<N_NODES / 8, 256>>>(W2, as2, ad2);
    kA2     <<<N_NODES / 8, 256>>>(b2, out);
}